// round 10
// baseline (speedup 1.0000x reference)
#include <cuda_runtime.h>
#include <math.h>

#define NN 2048
#define EE 65536
#define EP (EE + NN)
#define HID 64
#define HEADS 4
#define HD 16
#define KC 25
#define PRED_DIM 7

__device__ float g_h0[NN*HID];
__device__ float g_h1[NN*HID];
__device__ float g_h2[NN*HID];
__device__ float g_bufA[NN*HID];
__device__ float g_bufB[NN*HID];
__device__ float g_tmp[NN*HID];
__device__ float g_acc[NN*HID];
__device__ float g_m[NN*HEADS];
__device__ float g_denom[NN*HEADS];
__device__ float g_logits[EP*HEADS];
__device__ float g_loop[NN*6];
__device__ float g_sums[NN*6];
__device__ int   g_cnt[NN];
__device__ int   g_idx[KC];
__device__ float g_feats[KC*HID];

__device__ __forceinline__ void atomicMaxF(float* addr, float val){
    int* ai = (int*)addr;
    int old = *ai;
    while (__int_as_float(old) < val){
        int assumed = old;
        old = atomicCAS(ai, assumed, __float_as_int(val));
        if (old == assumed) break;
    }
}

__device__ __forceinline__ void tf2x32(unsigned k0, unsigned k1, unsigned x0, unsigned x1,
                                       unsigned& o0, unsigned& o1){
    unsigned ks2 = k0 ^ k1 ^ 0x1BD11BDAu;
    x0 += k0; x1 += k1;
#define TFR(r) { x0 += x1; x1 = (x1 << (r)) | (x1 >> (32 - (r))); x1 ^= x0; }
    TFR(13) TFR(15) TFR(26) TFR(6)
    x0 += k1; x1 += ks2 + 1u;
    TFR(17) TFR(29) TFR(16) TFR(24)
    x0 += ks2; x1 += k0 + 2u;
    TFR(13) TFR(15) TFR(26) TFR(6)
    x0 += k0; x1 += k1 + 3u;
    TFR(17) TFR(29) TFR(16) TFR(24)
    x0 += k1; x1 += ks2 + 4u;
    TFR(13) TFR(15) TFR(26) TFR(6)
    x0 += ks2; x1 += k0 + 5u;
#undef TFR
    o0 = x0; o1 = x1;
}

__device__ __forceinline__ unsigned tf_bits32(unsigned k0, unsigned k1, unsigned i){
    unsigned o0, o1;
    tf2x32(k0, k1, 0u, i, o0, o1);
    return o0 ^ o1;
}

__device__ __forceinline__ float gumbel_from_bits(unsigned b){
    const float TINY = 1.17549435e-38f;
    float f = __uint_as_float((b >> 9) | 0x3f800000u) - 1.0f;
    float u = fmaxf(TINY, f*(1.0f - TINY) + TINY);
    return -logf(-logf(u));
}

__global__ void enc1_kernel(const float* __restrict__ x, const float* __restrict__ pos,
                            const int* __restrict__ ntype, const float* __restrict__ temb,
                            const float* __restrict__ w1, const float* __restrict__ b1,
                            float* __restrict__ out){
    __shared__ float ws[15*HID];
    for (int i = threadIdx.x; i < 15*HID; i += blockDim.x) ws[i] = w1[i];
    __syncthreads();
    int idx = blockIdx.x*blockDim.x + threadIdx.x;
    if (idx >= NN*HID) return;
    int n = idx >> 6, c = idx & 63;
    float nf[15];
    nf[0]=x[n*4+0]; nf[1]=x[n*4+1]; nf[2]=x[n*4+2]; nf[3]=x[n*4+3];
    nf[4]=pos[n*3+0]; nf[5]=pos[n*3+1]; nf[6]=pos[n*3+2];
    int t = ntype[n];
    #pragma unroll
    for (int d=0; d<8; d++) nf[7+d] = temb[t*8+d];
    float acc = b1[c];
    #pragma unroll
    for (int d=0; d<15; d++) acc += nf[d]*ws[d*HID+c];
    out[idx] = fmaxf(acc, 0.f);
}

__global__ void gemm64_kernel(const float* __restrict__ in, const float* __restrict__ w,
                              const float* __restrict__ b, float* __restrict__ out, int act){
    __shared__ float ws[HID*HID];
    __shared__ float ins[4][HID];
    int tid = threadIdx.x;
    for (int i = tid; i < HID*HID; i += 256) ws[i] = w[i];
    int r = tid >> 6, c = tid & 63;
    int row = blockIdx.x*4 + r;
    ins[r][c] = in[row*HID + c];
    __syncthreads();
    float acc = b ? b[c] : 0.f;
    #pragma unroll
    for (int k=0;k<HID;k++) acc += ins[r][k]*ws[k*HID+c];
    if (act) acc = fmaxf(acc, 0.f);
    out[row*HID+c] = acc;
}

__global__ void loop_zero_kernel(){
    int i = blockIdx.x*blockDim.x+threadIdx.x;
    if (i < NN) g_cnt[i]=0;
    if (i < NN*6) g_sums[i]=0.f;
}
__global__ void loop_accum_kernel(const int* __restrict__ ei, const float* __restrict__ ea){
    int e = blockIdx.x*blockDim.x+threadIdx.x;
    if (e >= EE) return;
    int dst = ei[EE + e];
    atomicAdd(&g_cnt[dst], 1);
    #pragma unroll
    for (int d=0; d<6; d++) atomicAdd(&g_sums[dst*6+d], ea[e*6+d]);
}
__global__ void loop_fin_kernel(){
    int i = blockIdx.x*blockDim.x+threadIdx.x;
    if (i >= NN*6) return;
    g_loop[i] = g_sums[i] / fmaxf((float)g_cnt[i/6], 1.f);
}

__global__ void gat_init_kernel(){
    int i = blockIdx.x*blockDim.x+threadIdx.x;
    if (i < NN*HID) g_acc[i]=0.f;
    if (i < NN*HEADS){ g_m[i] = -3.4e38f; g_denom[i]=0.f; }
}

__global__ void gat_pass1_kernel(const int* __restrict__ ei, const float* __restrict__ ea,
                                 const float* __restrict__ we, const float* __restrict__ att,
                                 const float* __restrict__ xl, const float* __restrict__ xr){
    __shared__ float wes[6*HID];
    __shared__ float atts[HID];
    for (int i=threadIdx.x;i<6*HID;i+=blockDim.x) wes[i]=we[i];
    if (threadIdx.x < HID) atts[threadIdx.x]=att[threadIdx.x];
    __syncthreads();
    int gid = blockIdx.x*blockDim.x+threadIdx.x;
    if (gid >= EP*HEADS) return;
    int e = gid >> 2, h = gid & 3;
    int src, dst;
    float eav[6];
    if (e < EE){
        src = ei[e]; dst = ei[EE+e];
        #pragma unroll
        for (int d=0;d<6;d++) eav[d]=ea[e*6+d];
    } else {
        src = dst = e - EE;
        #pragma unroll
        for (int d=0;d<6;d++) eav[d]=g_loop[src*6+d];
    }
    int base = h*HD;
    const float* xls = xl + src*HID + base;
    const float* xrs = xr + dst*HID + base;
    float lo = 0.f;
    #pragma unroll
    for (int k=0;k<HD;k++){
        float v = xls[k] + xrs[k];
        #pragma unroll
        for (int d=0;d<6;d++) v += eav[d]*wes[d*HID+base+k];
        v = (v > 0.f) ? v : 0.2f*v;
        lo += v*atts[base+k];
    }
    g_logits[e*HEADS+h] = lo;
    atomicMaxF(&g_m[dst*HEADS+h], lo);
}

__global__ void gat_pass2_kernel(const int* __restrict__ ei, const float* __restrict__ xl){
    int gid = blockIdx.x*blockDim.x+threadIdx.x;
    if (gid >= EP*HEADS) return;
    int e = gid >> 2, h = gid & 3;
    int src, dst;
    if (e < EE){ src = ei[e]; dst = ei[EE+e]; } else { src = dst = e - EE; }
    float ex = expf(g_logits[e*HEADS+h] - g_m[dst*HEADS+h]);
    atomicAdd(&g_denom[dst*HEADS+h], ex);
    int base = h*HD;
    const float* xls = xl + src*HID + base;
    float* accp = g_acc + dst*HID + base;
    #pragma unroll
    for (int k=0;k<HD;k++) atomicAdd(&accp[k], xls[k]*ex);
}

__global__ void gat_pass3_kernel(const float* __restrict__ bias, float* __restrict__ hout, int act){
    int i = blockIdx.x*blockDim.x+threadIdx.x;
    if (i >= NN*HID) return;
    int n = i >> 6, c = i & 63;
    float v = g_acc[i] / g_denom[n*HEADS + (c>>4)] + bias[c];
    if (act) v = fmaxf(v, 0.f);
    hout[i] = v;
}

__global__ void __launch_bounds__(256) assoc_kernel(
        const float* __restrict__ si, const float* __restrict__ sj,
        const float* __restrict__ w2, const float* __restrict__ b2,
        float* __restrict__ A){
    __shared__ float sis[64][65];
    __shared__ float sjs[64][65];
    __shared__ float w2s[64];
    int tid = threadIdx.x;
    int bi = blockIdx.y*64, bj = blockIdx.x*64;
    for (int i=tid;i<64*64;i+=256){
        int r = i >> 6, c = i & 63;
        sis[r][c] = si[(bi+r)*HID + c];
        sjs[r][c] = sj[(bj+r)*HID + c];
    }
    if (tid < 64) w2s[tid] = w2[tid];
    __syncthreads();
    int tx = tid & 31, ty = tid >> 5;
    float acc[8][2];
    #pragma unroll
    for (int k=0;k<8;k++){ acc[k][0]=0.f; acc[k][1]=0.f; }
    #pragma unroll 4
    for (int c=0;c<64;c++){
        float w  = w2s[c];
        float v0 = sjs[tx][c], v1 = sjs[tx+32][c];
        #pragma unroll
        for (int k=0;k<8;k++){
            float a  = sis[ty + 8*k][c];
            acc[k][0] += fmaxf(a + v0, 0.f)*w;
            acc[k][1] += fmaxf(a + v1, 0.f)*w;
        }
    }
    float b2v = b2[0];
    #pragma unroll
    for (int k=0;k<8;k++){
        int gi = bi + ty + 8*k;
        float z0 = acc[k][0] + b2v, z1 = acc[k][1] + b2v;
        A[(size_t)gi*NN + bj + tx]      = 1.f/(1.f+expf(-z0));
        A[(size_t)gi*NN + bj + tx + 32] = 1.f/(1.f+expf(-z1));
    }
}

__global__ void __launch_bounds__(1024) cluster_kernel(const float* __restrict__ A){
    __shared__ float s_mind[NN];
    __shared__ float s_wv[32];
    __shared__ int   s_wi[32];
    __shared__ unsigned s_k0[KC-1], s_k1[KC-1];
    __shared__ int s_nxt;
    __shared__ float s_inv;
    __shared__ unsigned s_kq0, s_kq1;
    int tid = threadIdx.x;
    int lane = tid & 31, wid = tid >> 5;

    if (tid == 0){
        unsigned kf0,kf1, kq0,kq1;
        tf2x32(0u,42u, 0u,0u, kf0,kf1);   // kf
        tf2x32(0u,42u, 0u,1u, kq0,kq1);   // kseq
        s_kq0 = kq0; s_kq1 = kq1;
        // EXPERIMENT R8: split-based randint:
        //   k1,k2 = split(kf); lower_bits = random_bits(k2, 32, ())
        //   k2 = threefry(kf,(0,1)); lower = xor(threefry(k2,(0,0)))
        unsigned s2_0, s2_1;
        tf2x32(kf0, kf1, 0u, 1u, s2_0, s2_1);           // k2
        unsigned lower = tf_bits32(s2_0, s2_1, 0u);     // bits(k2, 32, ())
        int first = (int)(lower % (unsigned)NN);
        s_nxt = first;
        g_idx[0] = first;
    }
    __syncthreads();
    if (tid < KC-1){
        unsigned o0,o1;
        tf2x32(s_kq0, s_kq1, 0u, (unsigned)tid, o0, o1);
        s_k0[tid]=o0; s_k1[tid]=o1;
    }
    __syncthreads();
    {
        int first = s_nxt;
        s_mind[tid]      = 1.0f - A[(size_t)first*NN + tid];
        s_mind[tid+1024] = 1.0f - A[(size_t)first*NN + tid + 1024];
    }
    __syncthreads();

    for (int step=0; step<KC-1; step++){
        float s = s_mind[tid] + s_mind[tid+1024];
        #pragma unroll
        for (int o=16;o>0;o>>=1) s += __shfl_down_sync(0xffffffffu, s, o);
        if (lane==0) s_wv[wid]=s;
        __syncthreads();
        if (wid==0){
            float t = s_wv[lane];
            #pragma unroll
            for (int o=16;o>0;o>>=1) t += __shfl_down_sync(0xffffffffu, t, o);
            if (lane==0) s_inv = 1.0f/(t + 1e-8f);
        }
        __syncthreads();
        float inv = s_inv;
        unsigned b0 = tf_bits32(s_k0[step], s_k1[step], (unsigned)tid);
        unsigned b1 = tf_bits32(s_k0[step], s_k1[step], (unsigned)(tid+1024));
        float sc0 = logf(fmaxf(s_mind[tid]*inv,      1e-30f)) + gumbel_from_bits(b0);
        float sc1 = logf(fmaxf(s_mind[tid+1024]*inv, 1e-30f)) + gumbel_from_bits(b1);
        float bv; int bi;
        if (sc0 >= sc1){ bv = sc0; bi = tid; } else { bv = sc1; bi = tid + 1024; }
        #pragma unroll
        for (int o=16;o>0;o>>=1){
            float ov = __shfl_down_sync(0xffffffffu, bv, o);
            int   oi = __shfl_down_sync(0xffffffffu, bi, o);
            if (ov > bv || (ov == bv && oi < bi)){ bv = ov; bi = oi; }
        }
        if (lane==0){ s_wv[wid]=bv; s_wi[wid]=bi; }
        __syncthreads();
        if (wid==0){
            float v = s_wv[lane]; int ix = s_wi[lane];
            #pragma unroll
            for (int o=16;o>0;o>>=1){
                float ov = __shfl_down_sync(0xffffffffu, v, o);
                int   oi = __shfl_down_sync(0xffffffffu, ix, o);
                if (ov > v || (ov == v && oi < ix)){ v = ov; ix = oi; }
            }
            if (lane==0){ s_nxt = ix; g_idx[step+1] = ix; }
        }
        __syncthreads();
        int nxt = s_nxt;
        s_mind[tid]      = fminf(s_mind[tid],      1.0f - A[(size_t)nxt*NN + tid]);
        s_mind[tid+1024] = fminf(s_mind[tid+1024], 1.0f - A[(size_t)nxt*NN + tid + 1024]);
        __syncthreads();
    }
}

__global__ void assign_kernel(const float* __restrict__ A, float* __restrict__ assign){
    __shared__ int idxs[KC];
    if (threadIdx.x < KC) idxs[threadIdx.x] = g_idx[threadIdx.x];
    __syncthreads();
    int n = blockIdx.x*blockDim.x + threadIdx.x;
    if (n >= NN) return;
    float v[KC];
    float mx = -3.4e38f;
    #pragma unroll
    for (int k=0;k<KC;k++){
        v[k] = A[(size_t)n*NN + idxs[k]] * 10.0f;
        mx = fmaxf(mx, v[k]);
    }
    float sum = 0.f;
    #pragma unroll
    for (int k=0;k<KC;k++){ v[k] = expf(v[k]-mx); sum += v[k]; }
    float invs = 1.0f/sum;
    #pragma unroll
    for (int k=0;k<KC;k++) assign[n*KC+k] = v[k]*invs;
}

__global__ void feats_kernel(const float* __restrict__ assign, const float* __restrict__ h){
    int k = blockIdx.x, c = threadIdx.x;
    float acc = 0.f;
    for (int n=0;n<NN;n++) acc += assign[n*KC+k]*h[n*HID+c];
    g_feats[k*HID+c] = acc;
}

__global__ void preds_kernel(const float* __restrict__ w1, const float* __restrict__ b1,
                             const float* __restrict__ w2, const float* __restrict__ b2,
                             float* __restrict__ preds){
    __shared__ float hid[HID];
    int k = blockIdx.x, c = threadIdx.x;
    float acc = b1[c];
    #pragma unroll
    for (int d=0;d<HID;d++) acc += g_feats[k*HID+d]*w1[d*HID+c];
    hid[c] = fmaxf(acc, 0.f);
    __syncthreads();
    if (c < PRED_DIM){
        float p = b2[c];
        #pragma unroll
        for (int d=0;d<HID;d++) p += hid[d]*w2[d*PRED_DIM+c];
        preds[k*PRED_DIM+c] = p;
    }
}

extern "C" void kernel_launch(void* const* d_in, const int* in_sizes, int n_in,
                              void* d_out, int out_size) {
    const float* x        = (const float*)d_in[0];
    const float* pos      = (const float*)d_in[1];
    const int*   ntype    = (const int*)d_in[2];
    const int*   ei       = (const int*)d_in[3];
    const float* ea       = (const float*)d_in[4];
    const float* temb     = (const float*)d_in[5];
    const float* enc_w1   = (const float*)d_in[6];
    const float* enc_b1   = (const float*)d_in[7];
    const float* enc_w2   = (const float*)d_in[8];
    const float* enc_b2   = (const float*)d_in[9];
    const float* g1_wl  = (const float*)d_in[10];
    const float* g1_bl  = (const float*)d_in[11];
    const float* g1_wr  = (const float*)d_in[12];
    const float* g1_br  = (const float*)d_in[13];
    const float* g1_we  = (const float*)d_in[14];
    const float* g1_att = (const float*)d_in[15];
    const float* g1_bias= (const float*)d_in[16];
    const float* g2_wl  = (const float*)d_in[17];
    const float* g2_bl  = (const float*)d_in[18];
    const float* g2_wr  = (const float*)d_in[19];
    const float* g2_br  = (const float*)d_in[20];
    const float* g2_we  = (const float*)d_in[21];
    const float* g2_att = (const float*)d_in[22];
    const float* g2_bias= (const float*)d_in[23];
    const float* ah_w1  = (const float*)d_in[24];
    const float* ah_b1  = (const float*)d_in[25];
    const float* ah_w2  = (const float*)d_in[26];
    const float* ah_b2  = (const float*)d_in[27];
    const float* dec_w1 = (const float*)d_in[28];
    const float* dec_b1 = (const float*)d_in[29];
    const float* dec_w2 = (const float*)d_in[30];
    const float* dec_b2 = (const float*)d_in[31];

    float* out      = (float*)d_out;
    float* predsOut = out;
    float* Aout     = out + KC*PRED_DIM;
    float* assignO  = Aout + (size_t)NN*NN;

    float *h0, *h1, *h2, *bA, *bB, *tmp;
    cudaGetSymbolAddress((void**)&h0,  g_h0);
    cudaGetSymbolAddress((void**)&h1,  g_h1);
    cudaGetSymbolAddress((void**)&h2,  g_h2);
    cudaGetSymbolAddress((void**)&bA,  g_bufA);
    cudaGetSymbolAddress((void**)&bB,  g_bufB);
    cudaGetSymbolAddress((void**)&tmp, g_tmp);

    const int EHT = ((EP*HEADS)+255)/256;

    enc1_kernel<<<(NN*HID+255)/256, 256>>>(x, pos, ntype, temb, enc_w1, enc_b1, tmp);
    gemm64_kernel<<<NN/4, 256>>>(tmp, enc_w2, enc_b2, h0, 0);

    loop_zero_kernel<<<(NN*6+255)/256, 256>>>();
    loop_accum_kernel<<<EE/256, 256>>>(ei, ea);
    loop_fin_kernel<<<(NN*6+255)/256, 256>>>();

    gemm64_kernel<<<NN/4, 256>>>(h0, g1_wl, g1_bl, bA, 0);
    gemm64_kernel<<<NN/4, 256>>>(h0, g1_wr, g1_br, bB, 0);
    gat_init_kernel<<<(NN*HID+255)/256, 256>>>();
    gat_pass1_kernel<<<EHT, 256>>>(ei, ea, g1_we, g1_att, bA, bB);
    gat_pass2_kernel<<<EHT, 256>>>(ei, bA);
    gat_pass3_kernel<<<(NN*HID+255)/256, 256>>>(g1_bias, h1, 1);

    gemm64_kernel<<<NN/4, 256>>>(h1, g2_wl, g2_bl, bA, 0);
    gemm64_kernel<<<NN/4, 256>>>(h1, g2_wr, g2_br, bB, 0);
    gat_init_kernel<<<(NN*HID+255)/256, 256>>>();
    gat_pass1_kernel<<<EHT, 256>>>(ei, ea, g2_we, g2_att, bA, bB);
    gat_pass2_kernel<<<EHT, 256>>>(ei, bA);
    gat_pass3_kernel<<<(NN*HID+255)/256, 256>>>(g2_bias, h2, 0);

    gemm64_kernel<<<NN/4, 256>>>(h2, ah_w1,            ah_b1,   bA, 0);
    gemm64_kernel<<<NN/4, 256>>>(h2, ah_w1 + HID*HID,  nullptr, bB, 0);
    assoc_kernel<<<dim3(NN/64, NN/64), 256>>>(bA, bB, ah_w2, ah_b2, Aout);

    cluster_kernel<<<1, 1024>>>(Aout);
    assign_kernel<<<NN/256, 256>>>(Aout, assignO);
    feats_kernel<<<KC, HID>>>(assignO, h2);
    preds_kernel<<<KC, HID>>>(dec_w1, dec_b1, dec_w2, dec_b2, predsOut);
}

// round 13
// speedup vs baseline: 1.6581x; 1.6581x over previous
#include <cuda_runtime.h>
#include <math.h>

#define NN 2048
#define EE 65536
#define EP (EE + NN)
#define HID 64
#define HEADS 4
#define HD 16
#define KC 25
#define PRED_DIM 7

typedef unsigned long long ull;

__device__ float g_h0[NN*HID];
__device__ float g_h1[NN*HID];
__device__ float g_h2[NN*HID];
__device__ float g_bufA[NN*HID];
__device__ float g_bufB[NN*HID];
__device__ float g_tmp[NN*HID];
__device__ __align__(16) float g_acc[NN*HID];
__device__ float g_m[NN*HEADS];
__device__ float g_denom[NN*HEADS];
__device__ float g_logits[EP*HEADS];
__device__ float g_loop[NN*6];
__device__ __align__(16) float g_sums[NN*8];
__device__ int   g_idx[KC];
__device__ float g_feats[KC*HID];

// ---- ordered-float encoding for atomicMax on unsigned ----
// encode: neg -> ~b (MSB clear), pos -> b|0x80000000 (MSB set)
__device__ __forceinline__ unsigned f2ord(float f){
    unsigned b = __float_as_uint(f);
    return (b & 0x80000000u) ? ~b : (b | 0x80000000u);
}
// decode: MSB set -> positive (clear MSB); MSB clear -> negative (~u)
__device__ __forceinline__ float ord2f(unsigned u){
    return (u & 0x80000000u) ? __uint_as_float(u & 0x7FFFFFFFu) : __uint_as_float(~u);
}

// ---- packed f32x2 ----
__device__ __forceinline__ ull px2_add(ull a, ull b){
    ull r; asm("add.rn.f32x2 %0,%1,%2;" : "=l"(r) : "l"(a), "l"(b)); return r;
}
__device__ __forceinline__ ull px2_fma(ull a, ull b, ull c){
    ull r; asm("fma.rn.f32x2 %0,%1,%2,%3;" : "=l"(r) : "l"(a), "l"(b), "l"(c)); return r;
}
__device__ __forceinline__ ull px2_dup(float x){
    ull r; asm("mov.b64 %0,{%1,%1};" : "=l"(r) : "f"(x)); return r;
}

#define RED4(ptr, a,b,c,d) \
    asm volatile("red.global.add.v4.f32 [%0], {%1,%2,%3,%4};" \
                 :: "l"(ptr), "f"(a), "f"(b), "f"(c), "f"(d) : "memory")

// ---- JAX threefry2x32 ----
__device__ __forceinline__ void tf2x32(unsigned k0, unsigned k1, unsigned x0, unsigned x1,
                                       unsigned& o0, unsigned& o1){
    unsigned ks2 = k0 ^ k1 ^ 0x1BD11BDAu;
    x0 += k0; x1 += k1;
#define TFR(r) { x0 += x1; x1 = (x1 << (r)) | (x1 >> (32 - (r))); x1 ^= x0; }
    TFR(13) TFR(15) TFR(26) TFR(6)
    x0 += k1; x1 += ks2 + 1u;
    TFR(17) TFR(29) TFR(16) TFR(24)
    x0 += ks2; x1 += k0 + 2u;
    TFR(13) TFR(15) TFR(26) TFR(6)
    x0 += k0; x1 += k1 + 3u;
    TFR(17) TFR(29) TFR(16) TFR(24)
    x0 += k1; x1 += ks2 + 4u;
    TFR(13) TFR(15) TFR(26) TFR(6)
    x0 += ks2; x1 += k0 + 5u;
#undef TFR
    o0 = x0; o1 = x1;
}
__device__ __forceinline__ unsigned tf_bits32(unsigned k0, unsigned k1, unsigned i){
    unsigned o0, o1;
    tf2x32(k0, k1, 0u, i, o0, o1);
    return o0 ^ o1;
}
__device__ __forceinline__ float gumbel_from_bits(unsigned b){
    const float TINY = 1.17549435e-38f;
    float f = __uint_as_float((b >> 9) | 0x3f800000u) - 1.0f;
    float u = fmaxf(TINY, f*(1.0f - TINY) + TINY);
    return -logf(-logf(u));
}

// ---- encoder L1 ----
__global__ void enc1_kernel(const float* __restrict__ x, const float* __restrict__ pos,
                            const int* __restrict__ ntype, const float* __restrict__ temb,
                            const float* __restrict__ w1, const float* __restrict__ b1,
                            float* __restrict__ out){
    __shared__ float ws[15*HID];
    for (int i = threadIdx.x; i < 15*HID; i += blockDim.x) ws[i] = w1[i];
    __syncthreads();
    int idx = blockIdx.x*blockDim.x + threadIdx.x;
    if (idx >= NN*HID) return;
    int n = idx >> 6, c = idx & 63;
    float nf[15];
    nf[0]=x[n*4+0]; nf[1]=x[n*4+1]; nf[2]=x[n*4+2]; nf[3]=x[n*4+3];
    nf[4]=pos[n*3+0]; nf[5]=pos[n*3+1]; nf[6]=pos[n*3+2];
    int t = ntype[n];
    #pragma unroll
    for (int d=0; d<8; d++) nf[7+d] = temb[t*8+d];
    float acc = b1[c];
    #pragma unroll
    for (int d=0; d<15; d++) acc += nf[d]*ws[d*HID+c];
    out[idx] = fmaxf(acc, 0.f);
}

// ---- single [N,64]x[64,64] ----
__global__ void gemm64_kernel(const float* __restrict__ in, const float* __restrict__ w,
                              const float* __restrict__ b, float* __restrict__ out, int act){
    __shared__ float ws[HID*HID];
    __shared__ float ins[4][HID];
    int tid = threadIdx.x;
    for (int i = tid; i < HID*HID; i += 256) ws[i] = w[i];
    int r = tid >> 6, c = tid & 63;
    int row = blockIdx.x*4 + r;
    ins[r][c] = in[row*HID + c];
    __syncthreads();
    float acc = b ? b[c] : 0.f;
    #pragma unroll
    for (int k=0;k<HID;k++) acc += ins[r][k]*ws[k*HID+c];
    if (act) acc = fmaxf(acc, 0.f);
    out[row*HID+c] = acc;
}

// ---- dual [N,64]x[64,64] (two weight sets, one input) ----
__global__ void gemm64_dual_kernel(const float* __restrict__ in,
                                   const float* __restrict__ wA, const float* __restrict__ bA,
                                   const float* __restrict__ wB, const float* __restrict__ bB,
                                   float* __restrict__ oA, float* __restrict__ oB){
    __shared__ float wsA[HID*HID];
    __shared__ float wsB[HID*HID];
    __shared__ float ins[4][HID];
    int tid = threadIdx.x;
    for (int i = tid; i < HID*HID; i += 256){ wsA[i] = wA[i]; wsB[i] = wB[i]; }
    int r = tid >> 6, c = tid & 63;
    int row = blockIdx.x*4 + r;
    ins[r][c] = in[row*HID + c];
    __syncthreads();
    float aA = bA ? bA[c] : 0.f;
    float aB = bB ? bB[c] : 0.f;
    #pragma unroll
    for (int k=0;k<HID;k++){
        float v = ins[r][k];
        aA += v*wsA[k*HID+c];
        aB += v*wsB[k*HID+c];
    }
    oA[row*HID+c] = aA;
    oB[row*HID+c] = aB;
}

// ---- self-loop attrs ----
__global__ void loop_zero_kernel(){
    int i = blockIdx.x*blockDim.x+threadIdx.x;
    if (i < NN*8) g_sums[i]=0.f;
}
__global__ void loop_accum_kernel(const int* __restrict__ ei, const float* __restrict__ ea){
    int e = blockIdx.x*blockDim.x+threadIdx.x;
    if (e >= EE) return;
    int dst = ei[EE + e];
    float2 e01 = *(const float2*)(ea + e*6);
    float2 e23 = *(const float2*)(ea + e*6 + 2);
    float2 e45 = *(const float2*)(ea + e*6 + 4);
    float* p = &g_sums[dst*8];
    RED4(p,   e01.x, e01.y, e23.x, e23.y);
    RED4(p+4, e45.x, e45.y, 1.0f, 0.0f);
}
__global__ void loop_fin_kernel(){
    int i = blockIdx.x*blockDim.x+threadIdx.x;
    if (i >= NN*6) return;
    int n = i/6, d = i%6;
    g_loop[i] = g_sums[n*8+d] / fmaxf(g_sums[n*8+6], 1.f);
}

// ---- GATv2 ----
__global__ void gat_init_kernel(){
    int i = blockIdx.x*blockDim.x+threadIdx.x;
    if (i < NN*HID) g_acc[i]=0.f;
    if (i < NN*HEADS){ g_m[i] = __uint_as_float(0x007FFFFFu); g_denom[i]=0.f; }  // f2ord(-inf)
}

__global__ void gat_pass1_kernel(const int* __restrict__ ei, const float* __restrict__ ea,
                                 const float* __restrict__ we, const float* __restrict__ att,
                                 const float* __restrict__ xl, const float* __restrict__ xr){
    __shared__ float wes[6*HID];
    __shared__ float atts[HID];
    for (int i=threadIdx.x;i<6*HID;i+=blockDim.x) wes[i]=we[i];
    if (threadIdx.x < HID) atts[threadIdx.x]=att[threadIdx.x];
    __syncthreads();
    int gid = blockIdx.x*blockDim.x+threadIdx.x;
    if (gid >= EP*HEADS) return;
    int e = gid >> 2, h = gid & 3;
    int src, dst;
    float eav[6];
    if (e < EE){
        src = ei[e]; dst = ei[EE+e];
        float2 e01 = *(const float2*)(ea + e*6);
        float2 e23 = *(const float2*)(ea + e*6 + 2);
        float2 e45 = *(const float2*)(ea + e*6 + 4);
        eav[0]=e01.x; eav[1]=e01.y; eav[2]=e23.x; eav[3]=e23.y; eav[4]=e45.x; eav[5]=e45.y;
    } else {
        src = dst = e - EE;
        float2 e01 = *(const float2*)(g_loop + src*6);
        float2 e23 = *(const float2*)(g_loop + src*6 + 2);
        float2 e45 = *(const float2*)(g_loop + src*6 + 4);
        eav[0]=e01.x; eav[1]=e01.y; eav[2]=e23.x; eav[3]=e23.y; eav[4]=e45.x; eav[5]=e45.y;
    }
    int base = h*HD;
    const float4* xl4 = (const float4*)(xl + src*HID + base);
    const float4* xr4 = (const float4*)(xr + dst*HID + base);
    float lv[16];
    #pragma unroll
    for (int q=0;q<4;q++){
        float4 L = xl4[q], R = xr4[q];
        lv[q*4+0]=L.x+R.x; lv[q*4+1]=L.y+R.y; lv[q*4+2]=L.z+R.z; lv[q*4+3]=L.w+R.w;
    }
    float lo = 0.f;
    #pragma unroll
    for (int k=0;k<HD;k++){
        float v = lv[k];
        #pragma unroll
        for (int d=0;d<6;d++) v += eav[d]*wes[d*HID+base+k];
        v = (v > 0.f) ? v : 0.2f*v;
        lo += v*atts[base+k];
    }
    g_logits[e*HEADS+h] = lo;
    atomicMax((unsigned*)&g_m[dst*HEADS+h], f2ord(lo));
}

__global__ void gat_pass2_kernel(const int* __restrict__ ei, const float* __restrict__ xl){
    int gid = blockIdx.x*blockDim.x+threadIdx.x;
    if (gid >= EP*HEADS) return;
    int e = gid >> 2, h = gid & 3;
    int src, dst;
    if (e < EE){ src = ei[e]; dst = ei[EE+e]; } else { src = dst = e - EE; }
    float m = ord2f(__float_as_uint(g_m[dst*HEADS+h]));
    float ex = expf(g_logits[e*HEADS+h] - m);
    atomicAdd(&g_denom[dst*HEADS+h], ex);
    int base = h*HD;
    const float4* xl4 = (const float4*)(xl + src*HID + base);
    float* accp = g_acc + dst*HID + base;
    #pragma unroll
    for (int q=0;q<4;q++){
        float4 L = xl4[q];
        RED4(accp + q*4, L.x*ex, L.y*ex, L.z*ex, L.w*ex);
    }
}

__global__ void gat_pass3_kernel(const float* __restrict__ bias, float* __restrict__ hout, int act){
    int i = blockIdx.x*blockDim.x+threadIdx.x;
    if (i >= NN*HID) return;
    int n = i >> 6, c = i & 63;
    float v = g_acc[i] / g_denom[n*HEADS + (c>>4)] + bias[c];
    if (act) v = fmaxf(v, 0.f);
    hout[i] = v;
}

// ---- association matrix: transposed smem + packed f32x2 ----
__global__ void __launch_bounds__(256) assoc_kernel(
        const float* __restrict__ si, const float* __restrict__ sj,
        const float* __restrict__ w2, const float* __restrict__ b2,
        float* __restrict__ A){
    __shared__ __align__(16) float sis[64][68];   // [c][i], stride 68 = 16B-aligned rows
    __shared__ __align__(16) float sjs[64][68];   // [c][j]
    __shared__ float w2h[64];                     // 0.5*w2
    int tid = threadIdx.x;
    int bi = blockIdx.y*64, bj = blockIdx.x*64;
    for (int i=tid;i<64*64;i+=256){
        int r = i >> 6, c = i & 63;
        sis[c][r] = si[(bi+r)*HID + c];
        sjs[c][r] = sj[(bj+r)*HID + c];
    }
    if (tid < 64) w2h[tid] = 0.5f*w2[tid];
    __syncthreads();
    int tx = tid & 31, ty = tid >> 5;  // tx: j-pair 0..31, ty: i-group 0..7
    int ib = 8*ty, jb = 2*tx;
    const ull MASK = 0x7FFFFFFF7FFFFFFFULL;
    ull acc[4][2];
    #pragma unroll
    for (int p=0;p<4;p++){ acc[p][0]=0ULL; acc[p][1]=0ULL; }
    #pragma unroll 8
    for (int c=0;c<64;c++){
        double2 A01 = *(const double2*)&sis[c][ib];      // pairs (i0,i1),(i2,i3)
        double2 A23 = *(const double2*)&sis[c][ib+4];
        ull ap[4] = { __double_as_longlong(A01.x), __double_as_longlong(A01.y),
                      __double_as_longlong(A23.x), __double_as_longlong(A23.y) };
        ull pv0 = px2_dup(sjs[c][jb]);
        ull pv1 = px2_dup(sjs[c][jb+1]);
        ull pw  = px2_dup(w2h[c]);
        #pragma unroll
        for (int p=0;p<4;p++){
            ull t0 = px2_add(ap[p], pv0);
            t0 = px2_add(t0, t0 & MASK);          // x + |x| = 2*relu(x), exact
            acc[p][0] = px2_fma(t0, pw, acc[p][0]);
            ull t1 = px2_add(ap[p], pv1);
            t1 = px2_add(t1, t1 & MASK);
            acc[p][1] = px2_fma(t1, pw, acc[p][1]);
        }
    }
    float b2v = b2[0];
    #pragma unroll
    for (int p=0;p<4;p++){
        float o00 = __uint_as_float((unsigned)(acc[p][0]));         // i even, j0
        float o01 = __uint_as_float((unsigned)(acc[p][0]>>32));     // i odd,  j0
        float o10 = __uint_as_float((unsigned)(acc[p][1]));         // i even, j1
        float o11 = __uint_as_float((unsigned)(acc[p][1]>>32));     // i odd,  j1
        int i0 = bi + ib + 2*p;
        size_t r0o = (size_t)i0*NN + bj + jb;
        size_t r1o = (size_t)(i0+1)*NN + bj + jb;
        // A is only 4B-aligned (out + 175 floats) — scalar stores required
        A[r0o]   = 1.f/(1.f+expf(-(o00+b2v)));
        A[r0o+1] = 1.f/(1.f+expf(-(o10+b2v)));
        A[r1o]   = 1.f/(1.f+expf(-(o01+b2v)));
        A[r1o+1] = 1.f/(1.f+expf(-(o11+b2v)));
    }
}

// ---- soft clustering (VERBATIM from passing R8 kernel; do not touch) ----
__global__ void __launch_bounds__(1024) cluster_kernel(const float* __restrict__ A){
    __shared__ float s_mind[NN];
    __shared__ float s_wv[32];
    __shared__ int   s_wi[32];
    __shared__ unsigned s_k0[KC-1], s_k1[KC-1];
    __shared__ int s_nxt;
    __shared__ float s_inv;
    __shared__ unsigned s_kq0, s_kq1;
    int tid = threadIdx.x;
    int lane = tid & 31, wid = tid >> 5;

    if (tid == 0){
        unsigned kf0,kf1, kq0,kq1;
        tf2x32(0u,42u, 0u,0u, kf0,kf1);   // kf
        tf2x32(0u,42u, 0u,1u, kq0,kq1);   // kseq
        s_kq0 = kq0; s_kq1 = kq1;
        unsigned s2_0, s2_1;
        tf2x32(kf0, kf1, 0u, 1u, s2_0, s2_1);           // k2 = split(kf)[1]
        unsigned lower = tf_bits32(s2_0, s2_1, 0u);     // bits(k2, 32, ())
        int first = (int)(lower % (unsigned)NN);
        s_nxt = first;
        g_idx[0] = first;
    }
    __syncthreads();
    if (tid < KC-1){
        unsigned o0,o1;
        tf2x32(s_kq0, s_kq1, 0u, (unsigned)tid, o0, o1);
        s_k0[tid]=o0; s_k1[tid]=o1;
    }
    __syncthreads();
    {
        int first = s_nxt;
        s_mind[tid]      = 1.0f - A[(size_t)first*NN + tid];
        s_mind[tid+1024] = 1.0f - A[(size_t)first*NN + tid + 1024];
    }
    __syncthreads();

    for (int step=0; step<KC-1; step++){
        float s = s_mind[tid] + s_mind[tid+1024];
        #pragma unroll
        for (int o=16;o>0;o>>=1) s += __shfl_down_sync(0xffffffffu, s, o);
        if (lane==0) s_wv[wid]=s;
        __syncthreads();
        if (wid==0){
            float t = s_wv[lane];
            #pragma unroll
            for (int o=16;o>0;o>>=1) t += __shfl_down_sync(0xffffffffu, t, o);
            if (lane==0) s_inv = 1.0f/(t + 1e-8f);
        }
        __syncthreads();
        float inv = s_inv;
        unsigned b0 = tf_bits32(s_k0[step], s_k1[step], (unsigned)tid);
        unsigned b1 = tf_bits32(s_k0[step], s_k1[step], (unsigned)(tid+1024));
        float sc0 = logf(fmaxf(s_mind[tid]*inv,      1e-30f)) + gumbel_from_bits(b0);
        float sc1 = logf(fmaxf(s_mind[tid+1024]*inv, 1e-30f)) + gumbel_from_bits(b1);
        float bv; int bi;
        if (sc0 >= sc1){ bv = sc0; bi = tid; } else { bv = sc1; bi = tid + 1024; }
        #pragma unroll
        for (int o=16;o>0;o>>=1){
            float ov = __shfl_down_sync(0xffffffffu, bv, o);
            int   oi = __shfl_down_sync(0xffffffffu, bi, o);
            if (ov > bv || (ov == bv && oi < bi)){ bv = ov; bi = oi; }
        }
        if (lane==0){ s_wv[wid]=bv; s_wi[wid]=bi; }
        __syncthreads();
        if (wid==0){
            float v = s_wv[lane]; int ix = s_wi[lane];
            #pragma unroll
            for (int o=16;o>0;o>>=1){
                float ov = __shfl_down_sync(0xffffffffu, v, o);
                int   oi = __shfl_down_sync(0xffffffffu, ix, o);
                if (ov > v || (ov == v && oi < ix)){ v = ov; ix = oi; }
            }
            if (lane==0){ s_nxt = ix; g_idx[step+1] = ix; }
        }
        __syncthreads();
        int nxt = s_nxt;
        s_mind[tid]      = fminf(s_mind[tid],      1.0f - A[(size_t)nxt*NN + tid]);
        s_mind[tid+1024] = fminf(s_mind[tid+1024], 1.0f - A[(size_t)nxt*NN + tid + 1024]);
        __syncthreads();
    }
}

// ---- assign ----
__global__ void assign_kernel(const float* __restrict__ A, float* __restrict__ assign){
    __shared__ int idxs[KC];
    if (threadIdx.x < KC) idxs[threadIdx.x] = g_idx[threadIdx.x];
    __syncthreads();
    int n = blockIdx.x*blockDim.x + threadIdx.x;
    if (n >= NN) return;
    float v[KC];
    float mx = -3.4e38f;
    #pragma unroll
    for (int k=0;k<KC;k++){
        v[k] = A[(size_t)n*NN + idxs[k]] * 10.0f;
        mx = fmaxf(mx, v[k]);
    }
    float sum = 0.f;
    #pragma unroll
    for (int k=0;k<KC;k++){ v[k] = expf(v[k]-mx); sum += v[k]; }
    float invs = 1.0f/sum;
    #pragma unroll
    for (int k=0;k<KC;k++) assign[n*KC+k] = v[k]*invs;
}

// ---- feats = assign.T @ h2 : 25 blocks x 256 thr, block-tiled, no atomics ----
__global__ void feats_kernel(const float* __restrict__ assign, const float* __restrict__ h){
    int k = blockIdx.x;
    int tid = threadIdx.x;
    int c = tid & 63, g = tid >> 6;     // 4 n-groups
    __shared__ float a_s[256];
    __shared__ float part[4][HID];
    float acc = 0.f;
    for (int n0=0; n0<NN; n0+=256){
        __syncthreads();
        a_s[tid] = assign[(n0+tid)*KC + k];
        __syncthreads();
        for (int nn=g; nn<256; nn+=4)
            acc += a_s[nn]*h[(size_t)(n0+nn)*HID + c];
    }
    part[g][c] = acc;
    __syncthreads();
    if (g == 0)
        g_feats[k*HID+c] = part[0][c]+part[1][c]+part[2][c]+part[3][c];
}

// ---- preds ----
__global__ void preds_kernel(const float* __restrict__ w1, const float* __restrict__ b1,
                             const float* __restrict__ w2, const float* __restrict__ b2,
                             float* __restrict__ preds){
    __shared__ float hid[HID];
    int k = blockIdx.x, c = threadIdx.x;
    float acc = b1[c];
    #pragma unroll
    for (int d=0;d<HID;d++) acc += g_feats[k*HID+d]*w1[d*HID+c];
    hid[c] = fmaxf(acc, 0.f);
    __syncthreads();
    if (c < PRED_DIM){
        float p = b2[c];
        #pragma unroll
        for (int d=0;d<HID;d++) p += hid[d]*w2[d*PRED_DIM+c];
        preds[k*PRED_DIM+c] = p;
    }
}

extern "C" void kernel_launch(void* const* d_in, const int* in_sizes, int n_in,
                              void* d_out, int out_size) {
    const float* x        = (const float*)d_in[0];
    const float* pos      = (const float*)d_in[1];
    const int*   ntype    = (const int*)d_in[2];
    const int*   ei       = (const int*)d_in[3];
    const float* ea       = (const float*)d_in[4];
    const float* temb     = (const float*)d_in[5];
    const float* enc_w1   = (const float*)d_in[6];
    const float* enc_b1   = (const float*)d_in[7];
    const float* enc_w2   = (const float*)d_in[8];
    const float* enc_b2   = (const float*)d_in[9];
    const float* g1_wl  = (const float*)d_in[10];
    const float* g1_bl  = (const float*)d_in[11];
    const float* g1_wr  = (const float*)d_in[12];
    const float* g1_br  = (const float*)d_in[13];
    const float* g1_we  = (const float*)d_in[14];
    const float* g1_att = (const float*)d_in[15];
    const float* g1_bias= (const float*)d_in[16];
    const float* g2_wl  = (const float*)d_in[17];
    const float* g2_bl  = (const float*)d_in[18];
    const float* g2_wr  = (const float*)d_in[19];
    const float* g2_br  = (const float*)d_in[20];
    const float* g2_we  = (const float*)d_in[21];
    const float* g2_att = (const float*)d_in[22];
    const float* g2_bias= (const float*)d_in[23];
    const float* ah_w1  = (const float*)d_in[24];
    const float* ah_b1  = (const float*)d_in[25];
    const float* ah_w2  = (const float*)d_in[26];
    const float* ah_b2  = (const float*)d_in[27];
    const float* dec_w1 = (const float*)d_in[28];
    const float* dec_b1 = (const float*)d_in[29];
    const float* dec_w2 = (const float*)d_in[30];
    const float* dec_b2 = (const float*)d_in[31];

    float* out      = (float*)d_out;
    float* predsOut = out;
    float* Aout     = out + KC*PRED_DIM;
    float* assignO  = Aout + (size_t)NN*NN;

    float *h0, *h1, *h2, *bA, *bB, *tmp;
    cudaGetSymbolAddress((void**)&h0,  g_h0);
    cudaGetSymbolAddress((void**)&h1,  g_h1);
    cudaGetSymbolAddress((void**)&h2,  g_h2);
    cudaGetSymbolAddress((void**)&bA,  g_bufA);
    cudaGetSymbolAddress((void**)&bB,  g_bufB);
    cudaGetSymbolAddress((void**)&tmp, g_tmp);

    const int EHT = ((EP*HEADS)+255)/256;

    enc1_kernel<<<(NN*HID+255)/256, 256>>>(x, pos, ntype, temb, enc_w1, enc_b1, tmp);
    gemm64_kernel<<<NN/4, 256>>>(tmp, enc_w2, enc_b2, h0, 0);

    loop_zero_kernel<<<(NN*8+255)/256, 256>>>();
    loop_accum_kernel<<<EE/256, 256>>>(ei, ea);
    loop_fin_kernel<<<(NN*6+255)/256, 256>>>();

    gemm64_dual_kernel<<<NN/4, 256>>>(h0, g1_wl, g1_bl, g1_wr, g1_br, bA, bB);
    gat_init_kernel<<<(NN*HID+255)/256, 256>>>();
    gat_pass1_kernel<<<EHT, 256>>>(ei, ea, g1_we, g1_att, bA, bB);
    gat_pass2_kernel<<<EHT, 256>>>(ei, bA);
    gat_pass3_kernel<<<(NN*HID+255)/256, 256>>>(g1_bias, h1, 1);

    gemm64_dual_kernel<<<NN/4, 256>>>(h1, g2_wl, g2_bl, g2_wr, g2_br, bA, bB);
    gat_init_kernel<<<(NN*HID+255)/256, 256>>>();
    gat_pass1_kernel<<<EHT, 256>>>(ei, ea, g2_we, g2_att, bA, bB);
    gat_pass2_kernel<<<EHT, 256>>>(ei, bA);
    gat_pass3_kernel<<<(NN*HID+255)/256, 256>>>(g2_bias, h2, 0);

    gemm64_dual_kernel<<<NN/4, 256>>>(h2, ah_w1, ah_b1, ah_w1 + HID*HID, nullptr, bA, bB);
    assoc_kernel<<<dim3(NN/64, NN/64), 256>>>(bA, bB, ah_w2, ah_b2, Aout);

    cluster_kernel<<<1, 1024>>>(Aout);
    assign_kernel<<<NN/256, 256>>>(Aout, assignO);
    feats_kernel<<<KC, 256>>>(assignO, h2);
    preds_kernel<<<KC, HID>>>(dec_w1, dec_b1, dec_w2, dec_b2, predsOut);
}